// round 2
// baseline (speedup 1.0000x reference)
#include <cuda_runtime.h>
#include <cuda_bf16.h>
#include <stdint.h>

// Problem constants (shapes fixed by the dataset).
#define MAXN 50000
#define MAXE 800000
#define HC   128      // H*C
#define NH   4        // heads
#define CC   32       // per-head channels
#define RR   8        // relations
#define DE   64       // edge dim

// ---------------- scratch (device globals; no allocation allowed) -------------
__device__ float    g_q[(size_t)MAXN * HC];
__device__ float    g_k[(size_t)MAXN * HC];
__device__ float    g_v[(size_t)MAXN * HC];
__device__ float    g_ex[(size_t)MAXE * NH];     // logits, then exp values
__device__ unsigned g_mmax[(size_t)MAXN * NH];   // order-encoded float max
__device__ float    g_denom[(size_t)MAXN * NH];
__device__ float    g_eW[RR * HC];               // edge_emb @ We  (8 x 128)

// order-preserving float<->uint encoding for atomicMax on floats
__device__ __forceinline__ unsigned ordf(float f) {
    unsigned u = __float_as_uint(f);
    return (u & 0x80000000u) ? ~u : (u | 0x80000000u);
}
__device__ __forceinline__ float unordf(unsigned u) {
    return __uint_as_float((u & 0x80000000u) ? (u & 0x7FFFFFFFu) : ~u);
}

// ---------------- init: mmax/denom reset + e-table (edge_emb @ We) ------------
__global__ void init_kernel(const float* __restrict__ edge_emb,
                            const float* __restrict__ We, int Nn) {
    int i = blockIdx.x * blockDim.x + threadIdx.x;
    if (i < Nn * NH) {
        g_mmax[i] = 0x007FFFFFu;   // ordf(-inf)
        g_denom[i] = 0.0f;
    }
    if (i < RR * HC) {
        int r = i >> 7, c = i & 127;
        float s = 0.0f;
#pragma unroll
        for (int d = 0; d < DE; d++) s += edge_emb[r * DE + d] * We[d * HC + c];
        g_eW[i] = s;
    }
}

// ---------------- GEMM: y = x @ W (K=128, Ncols=128) --------------------------
// blockIdx.y selects which weight/output: 0:q 1:k 2:v 3:skip(->d_out)
// 128x128 output tile per block, 256 threads, 8x8 micro-tile, KT=32 smem tiling.
__global__ __launch_bounds__(256, 2)
void gemm_kernel(const float* __restrict__ x,
                 const float* __restrict__ Wq, const float* __restrict__ Wk,
                 const float* __restrict__ Wv, const float* __restrict__ Wskip,
                 float* __restrict__ out, int Nn) {
    __shared__ __align__(16) float xs[128 * 36];   // 128 rows x 32 k, pad stride 36
    __shared__ __align__(16) float ws[32 * 132];   // 32 k x 128 cols, pad stride 132

    const int which = blockIdx.y;
    const float* W = (which == 0) ? Wq : (which == 1) ? Wk : (which == 2) ? Wv : Wskip;
    float* outp = (which == 0) ? g_q : (which == 1) ? g_k : (which == 2) ? g_v : out;

    const int row0 = blockIdx.x * 128;
    const int tid = threadIdx.x;
    const int tx = tid & 15, ty = tid >> 4;

    float acc[8][8];
#pragma unroll
    for (int i = 0; i < 8; i++)
#pragma unroll
        for (int j = 0; j < 8; j++) acc[i][j] = 0.0f;

    for (int ko = 0; ko < 128; ko += 32) {
        // load x tile: rows row0..row0+127, cols ko..ko+31
#pragma unroll
        for (int t = 0; t < 4; t++) {
            int i = tid + t * 256;           // 0..1023, each = one float4
            int r = i >> 3, c4 = i & 7;
            int row = row0 + r;
            float4 vv = make_float4(0.f, 0.f, 0.f, 0.f);
            if (row < Nn) vv = *(const float4*)&x[(size_t)row * 128 + ko + c4 * 4];
            *(float4*)&xs[r * 36 + c4 * 4] = vv;
        }
        // load W tile: rows ko..ko+31, cols 0..127
#pragma unroll
        for (int t = 0; t < 4; t++) {
            int i = tid + t * 256;           // 0..1023 float4s
            int kr = i >> 5, c4 = i & 31;
            float4 vv = *(const float4*)&W[(size_t)(ko + kr) * 128 + c4 * 4];
            *(float4*)&ws[kr * 132 + c4 * 4] = vv;
        }
        __syncthreads();

#pragma unroll
        for (int kk = 0; kk < 32; kk++) {
            float a[8], b[8];
#pragma unroll
            for (int i = 0; i < 8; i++) a[i] = xs[(ty + 16 * i) * 36 + kk];
#pragma unroll
            for (int j = 0; j < 8; j++) b[j] = ws[kk * 132 + tx + 16 * j];
#pragma unroll
            for (int i = 0; i < 8; i++)
#pragma unroll
                for (int j = 0; j < 8; j++) acc[i][j] = fmaf(a[i], b[j], acc[i][j]);
        }
        __syncthreads();
    }

#pragma unroll
    for (int i = 0; i < 8; i++) {
        int row = row0 + ty + 16 * i;
        if (row < Nn) {
#pragma unroll
            for (int j = 0; j < 8; j++)
                outp[(size_t)row * 128 + tx + 16 * j] = acc[i][j];
        }
    }
}

// ---------------- pass 1: per-edge logits + segment max (warp/edge) -----------
__global__ void edge_logits_kernel(const int* __restrict__ ei,
                                   const int* __restrict__ et, int E_) {
    int gw = (int)((blockIdx.x * (unsigned)blockDim.x + threadIdx.x) >> 5);
    int lane = threadIdx.x & 31;
    if (gw >= E_) return;
    int src = ei[gw];
    int dst = ei[E_ + gw];
    int r = et[gw];

    float4 qd = *(const float4*)&g_q[(size_t)dst * 128 + lane * 4];
    float4 kk = *(const float4*)&g_k[(size_t)src * 128 + lane * 4];
    float4 ee = *(const float4*)&g_eW[r * 128 + lane * 4];

    float s = (kk.x + ee.x) * qd.x + (kk.y + ee.y) * qd.y +
              (kk.z + ee.z) * qd.z + (kk.w + ee.w) * qd.w;
    s += __shfl_xor_sync(0xFFFFFFFFu, s, 1);
    s += __shfl_xor_sync(0xFFFFFFFFu, s, 2);
    s += __shfl_xor_sync(0xFFFFFFFFu, s, 4);

    if ((lane & 7) == 0) {
        int h = lane >> 3;
        float logit = s * 0.17677669529663687f;   // 1/sqrt(32)
        g_ex[(size_t)gw * NH + h] = logit;
        atomicMax(&g_mmax[dst * NH + h], ordf(logit));
    }
}

// ---------------- pass 2: exp + segment sum -----------------------------------
__global__ void edge_exp_kernel(const int* __restrict__ ei, int E_) {
    int idx = blockIdx.x * blockDim.x + threadIdx.x;
    if (idx >= E_ * NH) return;
    int e = idx >> 2, h = idx & 3;
    int dst = ei[E_ + e];
    float m = unordf(g_mmax[dst * NH + h]);
    float ex = __expf(g_ex[idx] - m);
    g_ex[idx] = ex;
    atomicAdd(&g_denom[dst * NH + h], ex);
}

// ---------------- pass 3: weighted message scatter (warp/edge) ----------------
__global__ void edge_scatter_kernel(const int* __restrict__ ei,
                                    const int* __restrict__ et,
                                    float* __restrict__ out, int E_) {
    int gw = (int)((blockIdx.x * (unsigned)blockDim.x + threadIdx.x) >> 5);
    int lane = threadIdx.x & 31;
    if (gw >= E_) return;
    int src = ei[gw];
    int dst = ei[E_ + gw];
    int r = et[gw];
    int h = lane >> 3;

    float alpha = g_ex[(size_t)gw * NH + h] / (g_denom[dst * NH + h] + 1e-16f);
    float4 vv = *(const float4*)&g_v[(size_t)src * 128 + lane * 4];
    float4 ee = *(const float4*)&g_eW[r * 128 + lane * 4];

    float* op = out + (size_t)dst * 128 + lane * 4;
    atomicAdd(op + 0, (vv.x + ee.x) * alpha);
    atomicAdd(op + 1, (vv.y + ee.y) * alpha);
    atomicAdd(op + 2, (vv.z + ee.z) * alpha);
    atomicAdd(op + 3, (vv.w + ee.w) * alpha);
}

// ---------------- launch ------------------------------------------------------
extern "C" void kernel_launch(void* const* d_in, const int* in_sizes, int n_in,
                              void* d_out, int out_size) {
    const float* x        = (const float*)d_in[0];
    const int*   ei       = (const int*)d_in[1];    // int32 (JAX x64 disabled)
    const int*   et       = (const int*)d_in[2];    // int32
    const float* edge_emb = (const float*)d_in[3];
    const float* Wq       = (const float*)d_in[4];
    const float* Wk       = (const float*)d_in[5];
    const float* Wv       = (const float*)d_in[6];
    const float* We       = (const float*)d_in[7];
    const float* Wskip    = (const float*)d_in[8];
    float*       out      = (float*)d_out;

    const int Nn = in_sizes[0] / HC;   // 50000
    const int E_ = in_sizes[1] / 2;    // 800000

    // 1) init maxes/denoms + e-table
    {
        int total = Nn * NH;  // >= RR*HC
        init_kernel<<<(total + 255) / 256, 256>>>(edge_emb, We, Nn);
    }
    // 2) fused QKV + skip GEMMs (skip written straight into d_out)
    {
        dim3 grid((Nn + 127) / 128, 4);
        gemm_kernel<<<grid, 256>>>(x, Wq, Wk, Wv, Wskip, out, Nn);
    }
    // 3) logits + segment max
    edge_logits_kernel<<<(E_ * 32 + 255) / 256, 256>>>(ei, et, E_);
    // 4) exp + segment sum
    edge_exp_kernel<<<(E_ * NH + 255) / 256, 256>>>(ei, E_);
    // 5) alpha-weighted scatter into out (on top of skip)
    edge_scatter_kernel<<<(E_ * 32 + 255) / 256, 256>>>(ei, et, out, E_);
}

// round 3
// speedup vs baseline: 1.8158x; 1.8158x over previous
#include <cuda_runtime.h>
#include <cuda_bf16.h>
#include <stdint.h>

#define MAXN 50000
#define MAXE 800000
#define HC   128
#define NH   4
#define CC   32
#define RR   8
#define DE   64
#define SCAN_CHUNK 256

// ---------------- scratch ----------------------------------------------------
__device__ float g_q[(size_t)MAXN * HC];
__device__ float g_k[(size_t)MAXN * HC];
__device__ float g_v[(size_t)MAXN * HC];
__device__ float g_eW[RR * HC];
__device__ int   g_cnt[MAXN];
__device__ int   g_off[MAXN + 1];
__device__ int   g_cur[MAXN];
__device__ int   g_eid[MAXE];
__device__ int   g_blk[512];

// ---------------- f32x2 helpers ----------------------------------------------
__device__ __forceinline__ unsigned long long pk2(float lo, float hi) {
    unsigned long long r;
    asm("mov.b64 %0, {%1, %2};" : "=l"(r) : "f"(lo), "f"(hi));
    return r;
}
__device__ __forceinline__ void upk2(unsigned long long v, float& lo, float& hi) {
    asm("mov.b64 {%0, %1}, %2;" : "=f"(lo), "=f"(hi) : "l"(v));
}
__device__ __forceinline__ unsigned long long fma2(unsigned long long a,
                                                   unsigned long long b,
                                                   unsigned long long c) {
    unsigned long long d;
    asm("fma.rn.f32x2 %0, %1, %2, %3;" : "=l"(d) : "l"(a), "l"(b), "l"(c));
    return d;
}

// ---------------- init: zero counts + eW table --------------------------------
__global__ void init_kernel(const float* __restrict__ edge_emb,
                            const float* __restrict__ We, int Nn) {
    int i = blockIdx.x * blockDim.x + threadIdx.x;
    if (i < Nn) g_cnt[i] = 0;
    if (i < RR * HC) {
        int r = i >> 7, c = i & 127;
        float s = 0.0f;
#pragma unroll
        for (int d = 0; d < DE; d++) s += edge_emb[r * DE + d] * We[d * HC + c];
        g_eW[i] = s;
    }
}

// ---------------- GEMM with f32x2 packed FMAs ---------------------------------
__global__ __launch_bounds__(256, 2)
void gemm_kernel(const float* __restrict__ x,
                 const float* __restrict__ Wq, const float* __restrict__ Wk,
                 const float* __restrict__ Wv, const float* __restrict__ Wskip,
                 float* __restrict__ out, int Nn) {
    __shared__ __align__(16) float xs[128 * 36];
    __shared__ __align__(16) float ws[32 * 132];

    const int which = blockIdx.y;
    const float* W = (which == 0) ? Wq : (which == 1) ? Wk : (which == 2) ? Wv : Wskip;
    float* outp = (which == 0) ? g_q : (which == 1) ? g_k : (which == 2) ? g_v : out;

    const int row0 = blockIdx.x * 128;
    const int tid = threadIdx.x;
    const int tx = tid & 15, ty = tid >> 4;

    unsigned long long acc2[8][4];
#pragma unroll
    for (int i = 0; i < 8; i++)
#pragma unroll
        for (int jj = 0; jj < 4; jj++) acc2[i][jj] = 0ull;

    for (int ko = 0; ko < 128; ko += 32) {
#pragma unroll
        for (int t = 0; t < 4; t++) {
            int i = tid + t * 256;
            int r = i >> 3, c4 = i & 7;
            int row = row0 + r;
            float4 vv = make_float4(0.f, 0.f, 0.f, 0.f);
            if (row < Nn) vv = *(const float4*)&x[(size_t)row * 128 + ko + c4 * 4];
            *(float4*)&xs[r * 36 + c4 * 4] = vv;
        }
#pragma unroll
        for (int t = 0; t < 4; t++) {
            int i = tid + t * 256;
            int kr = i >> 5, c4 = i & 31;
            float4 vv = *(const float4*)&W[(size_t)(ko + kr) * 128 + c4 * 4];
            *(float4*)&ws[kr * 132 + c4 * 4] = vv;
        }
        __syncthreads();

#pragma unroll
        for (int kk = 0; kk < 32; kk++) {
            unsigned long long a2[8], b2[4];
#pragma unroll
            for (int i = 0; i < 8; i++) {
                float a = xs[(ty + 16 * i) * 36 + kk];
                a2[i] = pk2(a, a);
            }
#pragma unroll
            for (int jj = 0; jj < 4; jj++)
                b2[jj] = *(const unsigned long long*)&ws[kk * 132 + 32 * jj + 2 * tx];
#pragma unroll
            for (int i = 0; i < 8; i++)
#pragma unroll
                for (int jj = 0; jj < 4; jj++)
                    acc2[i][jj] = fma2(a2[i], b2[jj], acc2[i][jj]);
        }
        __syncthreads();
    }

#pragma unroll
    for (int i = 0; i < 8; i++) {
        int row = row0 + ty + 16 * i;
        if (row < Nn) {
#pragma unroll
            for (int jj = 0; jj < 4; jj++) {
                float lo, hi;
                upk2(acc2[i][jj], lo, hi);
                float2 st = make_float2(lo, hi);
                *(float2*)&outp[(size_t)row * 128 + 32 * jj + 2 * tx] = st;
            }
        }
    }
}

// ---------------- CSR build ---------------------------------------------------
__global__ void count_kernel(const int* __restrict__ ei, int E_) {
    int i = blockIdx.x * blockDim.x + threadIdx.x;
    if (i < E_) atomicAdd(&g_cnt[ei[E_ + i]], 1);
}

__global__ void scanA_kernel(int Nn) {
    __shared__ int s[2][SCAN_CHUNK];
    int t = threadIdx.x, b = blockIdx.x;
    int i = b * SCAN_CHUNK + t;
    int v = (i < Nn) ? g_cnt[i] : 0;
    s[0][t] = v;
    int cur = 0;
#pragma unroll
    for (int d = 1; d < SCAN_CHUNK; d <<= 1) {
        __syncthreads();
        int val = s[cur][t] + ((t >= d) ? s[cur][t - d] : 0);
        s[cur ^ 1][t] = val;
        cur ^= 1;
    }
    __syncthreads();
    int inc = s[cur][t];
    if (i < Nn) g_off[i] = inc - v;           // local exclusive
    if (t == SCAN_CHUNK - 1) g_blk[b] = inc;  // block total
}

__global__ void scanB_kernel(int nblk) {
    __shared__ int s[2][512];
    int t = threadIdx.x;
    int v = (t < nblk) ? g_blk[t] : 0;
    s[0][t] = v;
    int cur = 0;
#pragma unroll
    for (int d = 1; d < 512; d <<= 1) {
        __syncthreads();
        int val = s[cur][t] + ((t >= d) ? s[cur][t - d] : 0);
        s[cur ^ 1][t] = val;
        cur ^= 1;
    }
    __syncthreads();
    if (t < nblk) g_blk[t] = s[cur][t] - v;   // exclusive block offsets
}

__global__ void scanC_kernel(int Nn, int E_) {
    int i = blockIdx.x * blockDim.x + threadIdx.x;
    if (i < Nn) {
        int o = g_off[i] + g_blk[i / SCAN_CHUNK];
        g_off[i] = o;
        g_cur[i] = o;
    }
    if (i == 0) g_off[Nn] = E_;
}

__global__ void fill_kernel(const int* __restrict__ ei, int E_) {
    int i = blockIdx.x * blockDim.x + threadIdx.x;
    if (i < E_) {
        int pos = atomicAdd(&g_cur[ei[E_ + i]], 1);
        g_eid[pos] = i;
    }
}

// ---------------- fused attention: warp per node, online softmax --------------
__global__ __launch_bounds__(256)
void node_kernel(const int* __restrict__ ei, const int* __restrict__ et,
                 float* __restrict__ out, int Nn, int E_) {
    int nid = (int)((blockIdx.x * (unsigned)blockDim.x + threadIdx.x) >> 5);
    int lane = threadIdx.x & 31;
    if (nid >= Nn) return;
    int beg = g_off[nid], end = g_off[nid + 1];
    if (beg == end) return;   // out keeps skip value

    float4 q = *(const float4*)&g_q[(size_t)nid * 128 + lane * 4];

    float m = -__int_as_float(0x7f800000);  // -inf
    float s = 0.0f;
    float4 acc = make_float4(0.f, 0.f, 0.f, 0.f);

    for (int p = beg; p < end; p++) {
        int e = g_eid[p];
        int src = ei[e];
        int r = et[e];

        float4 kk = *(const float4*)&g_k[(size_t)src * 128 + lane * 4];
        float4 ee = *(const float4*)&g_eW[r * 128 + lane * 4];
        float4 vv = *(const float4*)&g_v[(size_t)src * 128 + lane * 4];

        float t = (kk.x + ee.x) * q.x + (kk.y + ee.y) * q.y +
                  (kk.z + ee.z) * q.z + (kk.w + ee.w) * q.w;
        t += __shfl_xor_sync(0xFFFFFFFFu, t, 1);
        t += __shfl_xor_sync(0xFFFFFFFFu, t, 2);
        t += __shfl_xor_sync(0xFFFFFFFFu, t, 4);
        float logit = t * 0.17677669529663687f;   // 1/sqrt(32)

        float newm = fmaxf(m, logit);
        float scale = __expf(m - newm);   // first iter: exp(-inf) = 0
        float pr = __expf(logit - newm);
        s = s * scale + pr;
        acc.x = acc.x * scale + pr * (vv.x + ee.x);
        acc.y = acc.y * scale + pr * (vv.y + ee.y);
        acc.z = acc.z * scale + pr * (vv.z + ee.z);
        acc.w = acc.w * scale + pr * (vv.w + ee.w);
        m = newm;
    }

    float inv = 1.0f / (s + 1e-16f);
    float4 o = *(float4*)&out[(size_t)nid * 128 + lane * 4];
    o.x += acc.x * inv;
    o.y += acc.y * inv;
    o.z += acc.z * inv;
    o.w += acc.w * inv;
    *(float4*)&out[(size_t)nid * 128 + lane * 4] = o;
}

// ---------------- launch ------------------------------------------------------
extern "C" void kernel_launch(void* const* d_in, const int* in_sizes, int n_in,
                              void* d_out, int out_size) {
    const float* x        = (const float*)d_in[0];
    const int*   ei       = (const int*)d_in[1];
    const int*   et       = (const int*)d_in[2];
    const float* edge_emb = (const float*)d_in[3];
    const float* Wq       = (const float*)d_in[4];
    const float* Wk       = (const float*)d_in[5];
    const float* Wv       = (const float*)d_in[6];
    const float* We       = (const float*)d_in[7];
    const float* Wskip    = (const float*)d_in[8];
    float*       out      = (float*)d_out;

    const int Nn = in_sizes[0] / HC;   // 50000
    const int E_ = in_sizes[1] / 2;    // 800000
    const int nblk = (Nn + SCAN_CHUNK - 1) / SCAN_CHUNK;

    init_kernel<<<(Nn + 255) / 256, 256>>>(edge_emb, We, Nn);

    dim3 ggrid((Nn + 127) / 128, 4);
    gemm_kernel<<<ggrid, 256>>>(x, Wq, Wk, Wv, Wskip, out, Nn);

    count_kernel<<<(E_ + 255) / 256, 256>>>(ei, E_);
    scanA_kernel<<<nblk, SCAN_CHUNK>>>(Nn);
    scanB_kernel<<<1, 512>>>(nblk);
    scanC_kernel<<<(Nn + 255) / 256, 256>>>(Nn, E_);
    fill_kernel<<<(E_ + 255) / 256, 256>>>(ei, E_);

    node_kernel<<<(Nn * 32 + 255) / 256, 256>>>(ei, et, out, Nn, E_);
}